// round 15
// baseline (speedup 1.0000x reference)
#include <cuda_runtime.h>
#include <cuda_fp16.h>
#include <cuda_bf16.h>
#include <math.h>

#define N_NODES 50000
#define N_EDGES 1600000
#define IN_DIM  128
#define HID     64
#define EPS     1e-6f

#define SCAN_T   1024
#define NTILES   ((N_NODES + SCAN_T - 1) / SCAN_T)   // 49
#define FLAG     (1 << 30)
#define VMASK    (FLAG - 1)

#define NBLK     148        // co-resident persistent grid (1 block/SM)
#define NTHR     256

// ---------------- scratch (no allocations allowed) ----------------
__device__ int   g_is64;
__device__ __align__(16) int   g_deg[N_NODES];
__device__ __align__(16) int   g_rowptr[N_NODES + 4];
__device__ __align__(16) int   g_cursor[N_NODES];
__device__ __align__(16) float g_invdeg[N_NODES];
__device__ int   g_csr_src[N_EDGES];
__device__ int   g_tile_state[64];
__device__ int   g_barrier;

__device__ float  g_s[N_NODES * HID];
__device__ __half g_th[N_NODES * HID];
__device__ float  g_hA[N_NODES * HID];
__device__ float  g_hB[N_NODES * HID];

__device__ __forceinline__ int edge_at(const void* __restrict__ ei, int idx, int is64) {
    if (is64) return (int)((const long long*)ei)[idx];
    return ((const int*)ei)[idx];
}

// ---- f32x2 packed FMA helpers ----
__device__ __forceinline__ unsigned long long pk2(float lo, float hi) {
    unsigned long long r;
    asm("mov.b64 %0, {%1, %2};" : "=l"(r) : "f"(lo), "f"(hi));
    return r;
}
__device__ __forceinline__ void fma2(unsigned long long& d, unsigned long long a, unsigned long long b) {
    asm("fma.rn.f32x2 %0, %1, %2, %0;" : "+l"(d) : "l"(a), "l"(b));
}
__device__ __forceinline__ float fold2(unsigned long long p) {
    float lo, hi;
    asm("mov.b64 {%0, %1}, %2;" : "=f"(lo), "=f"(hi) : "l"(p));
    return lo + hi;
}

// ---------------- device-wide barrier (all NBLK blocks co-resident) ----------------
__device__ __forceinline__ void grid_barrier(int target) {
    __syncthreads();
    if (threadIdx.x == 0) {
        __threadfence();
        atomicAdd(&g_barrier, 1);
        while (atomicAdd(&g_barrier, 0) < target) __nanosleep(64);
        __threadfence();
    }
    __syncthreads();
}

// ---------------- init: zero deg + states, detect edge dtype ----------------
__global__ void init_kernel(const void* __restrict__ ei) {
    int i = blockIdx.x * blockDim.x + threadIdx.x;
    if (i < N_NODES) g_deg[i] = 0;
    if (blockIdx.x == 1 && threadIdx.x < 64) g_tile_state[threadIdx.x] = 0;
    if (blockIdx.x == 2 && threadIdx.x == 0) g_barrier = 0;
    if (blockIdx.x == 0) {
        const long long* p = (const long long*)ei;
        long long v = p[threadIdx.x];
        int bad = (v < 0 || v >= (long long)N_NODES) ? 1 : 0;
        int anybad = __syncthreads_or(bad);
        if (threadIdx.x == 0) g_is64 = anybad ? 0 : 1;
    }
}

// ---------------- stage: degree count ----------------
__device__ void count_stage(const void* __restrict__ ei, int is64) {
    int stride = NBLK * NTHR;
    for (int e = blockIdx.x * NTHR + threadIdx.x; e < N_EDGES; e += stride) {
        int dst = edge_at(ei, N_EDGES + e, is64);
        atomicAdd(&g_deg[dst], 1);
    }
}

// ---------------- stage: rowptr scan (decoupled lookback, blocks 0..48) ----------------
__device__ void scan_stage(float* smemf) {
    int* wsums = (int*)smemf;        // [8]
    int* red   = (int*)smemf + 8;    // [2]
    int* spref = (int*)smemf + 10;   // [1]
    int b = blockIdx.x, tid = threadIdx.x;
    if (b < NTILES) {
        int lane = tid & 31, wid = tid >> 5;
        int base = b * SCAN_T + tid * 4;
        int d0 = 0, d1 = 0, d2 = 0, d3 = 0;
        if (base + 3 < N_NODES) {
            int4 dd = *(const int4*)&g_deg[base];
            d0 = dd.x; d1 = dd.y; d2 = dd.z; d3 = dd.w;
        } else if (base < N_NODES) {
            d0 = g_deg[base];
            if (base + 1 < N_NODES) d1 = g_deg[base + 1];
            if (base + 2 < N_NODES) d2 = g_deg[base + 2];
        }
        int tsum = d0 + d1 + d2 + d3;
        int v = tsum;
        #pragma unroll
        for (int o = 1; o < 32; o <<= 1) {
            int u = __shfl_up_sync(0xffffffffu, v, o);
            if (lane >= o) v += u;
        }
        if (lane == 31) wsums[wid] = v;
        __syncthreads();
        if (wid == 0 && lane < 8) {
            int w = wsums[lane];
            #pragma unroll
            for (int o = 1; o < 8; o <<= 1) {
                int u = __shfl_up_sync(0xffu, w, o);
                if (lane >= o) w += u;
            }
            wsums[lane] = w;
        }
        __syncthreads();
        if (tid == 0) atomicExch(&g_tile_state[b], wsums[7] | FLAG);

        if (tid < 64) {
            int val = 0;
            if (tid < b) {
                int t;
                do { t = atomicAdd(&g_tile_state[tid], 0); } while (!(t & FLAG));
                val = t & VMASK;
            }
            #pragma unroll
            for (int o = 16; o; o >>= 1) val += __shfl_xor_sync(0xffffffffu, val, o);
            if ((tid & 31) == 0) red[tid >> 5] = val;
        }
        __syncthreads();
        if (tid == 0) *spref = red[0] + red[1];
        __syncthreads();

        int excl = *spref + (v - tsum) + (wid ? wsums[wid - 1] : 0);
        if (base + 3 < N_NODES) {
            int4 rp;
            rp.x = excl; rp.y = excl + d0; rp.z = excl + d0 + d1; rp.w = excl + d0 + d1 + d2;
            *(int4*)&g_rowptr[base] = rp;
            *(int4*)&g_cursor[base] = rp;
            float4 iv;
            iv.x = 1.0f / (float)max(d0, 1);
            iv.y = 1.0f / (float)max(d1, 1);
            iv.z = 1.0f / (float)max(d2, 1);
            iv.w = 1.0f / (float)max(d3, 1);
            *(float4*)&g_invdeg[base] = iv;
        } else if (base < N_NODES) {
            int r = excl;
            g_rowptr[base] = r; g_cursor[base] = r;
            g_invdeg[base] = 1.0f / (float)max(d0, 1);
            if (base + 1 < N_NODES) {
                r += d0; g_rowptr[base + 1] = r; g_cursor[base + 1] = r;
                g_invdeg[base + 1] = 1.0f / (float)max(d1, 1);
            }
            if (base + 2 < N_NODES) {
                r += d1; g_rowptr[base + 2] = r; g_cursor[base + 2] = r;
                g_invdeg[base + 2] = 1.0f / (float)max(d2, 1);
            }
        }
    }
    if (b == 0 && tid == 0) g_rowptr[N_NODES] = N_EDGES;
    __syncthreads();
}

// ---------------- stage: CSR fill ----------------
__device__ void fill_stage(const void* __restrict__ ei, int is64) {
    int stride = NBLK * NTHR;
    for (int e = blockIdx.x * NTHR + threadIdx.x; e < N_EDGES; e += stride) {
        int src = edge_at(ei, e, is64);
        int dst = edge_at(ei, N_EDGES + e, is64);
        int pos = atomicAdd(&g_cursor[dst], 1);
        g_csr_src[pos] = src;
    }
}

// ---------------- stage: dual GEMM (FFMA2, pair-interleaved weights in smem) ----------
template<int DIN>
__device__ void gemm_stage(const float* __restrict__ h,
                           const float* __restrict__ ws,
                           const float* __restrict__ wn,
                           float* __restrict__ s_out,
                           __half* __restrict__ t_out,
                           float* smem) {
    float* ws_p = smem;                        // DIN*64 (pair-interleaved)
    float* wn_p = smem + DIN * 64;
    float* h_sh = smem + 2 * DIN * 64;         // 32*DIN

    int tid = threadIdx.x;
    int tx  = tid & 31;
    int ty  = tid >> 5;

    for (int i = tid; i < DIN * 64; i += 256) {
        int k = i >> 6, c = i & 63;
        float vs = ws[i], vn = wn[i];
        int d = ((k >> 1) << 7) + (c << 1) + (k & 1);
        ws_p[d] = vs;
        wn_p[d] = vn;
    }
    __syncthreads();

    const float4* ws_p4 = (const float4*)ws_p;
    const float4* wn_p4 = (const float4*)wn_p;

    const int NT32 = (N_NODES + 31) / 32;
    for (int t32 = blockIdx.x; t32 < NT32; t32 += gridDim.x) {
        int nb = t32 * 32;
        int vn_ = min(32, N_NODES - nb);
        int valid_f4 = vn_ * (DIN / 4);

        const float4* hsrc = (const float4*)(h + (size_t)nb * DIN);
        for (int i = tid; i < 32 * (DIN / 4); i += 256)
            ((float4*)h_sh)[i] = (i < valid_f4) ? hsrc[i] : make_float4(0.f, 0.f, 0.f, 0.f);
        __syncthreads();

        int row = ty * 4;
        const float4* h0 = (const float4*)(h_sh + (row + 0) * DIN);
        const float4* h1 = (const float4*)(h_sh + (row + 1) * DIN);
        const float4* h2 = (const float4*)(h_sh + (row + 2) * DIN);
        const float4* h3 = (const float4*)(h_sh + (row + 3) * DIN);

        unsigned long long sc0[4] = {0,0,0,0}, sc1[4] = {0,0,0,0};
        unsigned long long tc0[4] = {0,0,0,0}, tc1[4] = {0,0,0,0};

        #pragma unroll 2
        for (int kq = 0; kq < DIN / 4; ++kq) {
            float4 v0 = h0[kq], v1 = h1[kq], v2 = h2[kq], v3 = h3[kq];
            float4 wsA = ws_p4[(2 * kq) * 32 + tx];
            float4 wsB = ws_p4[(2 * kq + 1) * 32 + tx];
            float4 wnA = wn_p4[(2 * kq) * 32 + tx];
            float4 wnB = wn_p4[(2 * kq + 1) * 32 + tx];

            unsigned long long wsA0 = pk2(wsA.x, wsA.y), wsA1 = pk2(wsA.z, wsA.w);
            unsigned long long wsB0 = pk2(wsB.x, wsB.y), wsB1 = pk2(wsB.z, wsB.w);
            unsigned long long wnA0 = pk2(wnA.x, wnA.y), wnA1 = pk2(wnA.z, wnA.w);
            unsigned long long wnB0 = pk2(wnB.x, wnB.y), wnB1 = pk2(wnB.z, wnB.w);

            unsigned long long aA[4], aB[4];
            aA[0] = pk2(v0.x, v0.y); aB[0] = pk2(v0.z, v0.w);
            aA[1] = pk2(v1.x, v1.y); aB[1] = pk2(v1.z, v1.w);
            aA[2] = pk2(v2.x, v2.y); aB[2] = pk2(v2.z, v2.w);
            aA[3] = pk2(v3.x, v3.y); aB[3] = pk2(v3.z, v3.w);

            #pragma unroll
            for (int n = 0; n < 4; ++n) {
                fma2(sc0[n], aA[n], wsA0); fma2(sc1[n], aA[n], wsA1);
                fma2(tc0[n], aA[n], wnA0); fma2(tc1[n], aA[n], wnA1);
                fma2(sc0[n], aB[n], wsB0); fma2(sc1[n], aB[n], wsB1);
                fma2(tc0[n], aB[n], wnB0); fma2(tc1[n], aB[n], wnB1);
            }
        }

        #pragma unroll
        for (int n = 0; n < 4; ++n) {
            int node = nb + row + n;
            if (node < N_NODES) {
                float2 sv; sv.x = fold2(sc0[n]); sv.y = fold2(sc1[n]);
                float2 tv; tv.x = fold2(tc0[n]); tv.y = fold2(tc1[n]);
                *(float2*)&s_out[(size_t)node * 64 + 2 * tx] = sv;
                *(__half2*)&t_out[(size_t)node * 64 + 2 * tx] = __float22half2_rn(tv);
            }
        }
        __syncthreads();
    }
}

// ---------------- stage: aggregate + combine + normalize (quarter-warp/node) -------
__device__ void agg_stage(const __half* __restrict__ t,
                          const float* __restrict__ smat,
                          float* __restrict__ hout) {
    int gw   = (blockIdx.x * NTHR + threadIdx.x) >> 5;
    int lane = threadIdx.x & 31;
    int sub  = lane >> 3;
    int sl   = lane & 7;
    const int slots = (NBLK * NTHR) >> 3;   // quarter-warps total

    for (int node = gw * 4 + sub; node < N_NODES; node += slots) {
        int beg = g_rowptr[node];
        int end = g_rowptr[node + 1];

        float a0=0.f,a1=0.f,a2=0.f,a3=0.f,a4=0.f,a5=0.f,a6=0.f,a7=0.f;

        int i = beg;
        for (; i + 2 <= end; i += 2) {
            int s0 = __ldg(&g_csr_src[i]);
            int s1 = __ldg(&g_csr_src[i + 1]);
            uint4 r0 = __ldg((const uint4*)(t + (size_t)s0 * 64 + sl * 8));
            uint4 r1 = __ldg((const uint4*)(t + (size_t)s1 * 64 + sl * 8));
            float2 f0 = __half22float2(*(__half2*)&r0.x);
            float2 f1 = __half22float2(*(__half2*)&r0.y);
            float2 f2 = __half22float2(*(__half2*)&r0.z);
            float2 f3 = __half22float2(*(__half2*)&r0.w);
            a0 += f0.x; a1 += f0.y; a2 += f1.x; a3 += f1.y;
            a4 += f2.x; a5 += f2.y; a6 += f3.x; a7 += f3.y;
            float2 g0 = __half22float2(*(__half2*)&r1.x);
            float2 g1 = __half22float2(*(__half2*)&r1.y);
            float2 g2 = __half22float2(*(__half2*)&r1.z);
            float2 g3 = __half22float2(*(__half2*)&r1.w);
            a0 += g0.x; a1 += g0.y; a2 += g1.x; a3 += g1.y;
            a4 += g2.x; a5 += g2.y; a6 += g3.x; a7 += g3.y;
        }
        if (i < end) {
            int s0 = __ldg(&g_csr_src[i]);
            uint4 r0 = __ldg((const uint4*)(t + (size_t)s0 * 64 + sl * 8));
            float2 f0 = __half22float2(*(__half2*)&r0.x);
            float2 f1 = __half22float2(*(__half2*)&r0.y);
            float2 f2 = __half22float2(*(__half2*)&r0.z);
            float2 f3 = __half22float2(*(__half2*)&r0.w);
            a0 += f0.x; a1 += f0.y; a2 += f1.x; a3 += f1.y;
            a4 += f2.x; a5 += f2.y; a6 += f3.x; a7 += f3.y;
        }

        float id = g_invdeg[node];
        float4 sm0 = __ldg((const float4*)(smat + (size_t)node * 64 + sl * 8));
        float4 sm1 = __ldg((const float4*)(smat + (size_t)node * 64 + sl * 8 + 4));
        float v0 = fmaxf(sm0.x + a0 * id, 0.f);
        float v1 = fmaxf(sm0.y + a1 * id, 0.f);
        float v2 = fmaxf(sm0.z + a2 * id, 0.f);
        float v3 = fmaxf(sm0.w + a3 * id, 0.f);
        float v4 = fmaxf(sm1.x + a4 * id, 0.f);
        float v5 = fmaxf(sm1.y + a5 * id, 0.f);
        float v6 = fmaxf(sm1.z + a6 * id, 0.f);
        float v7 = fmaxf(sm1.w + a7 * id, 0.f);

        float ss = v0*v0 + v1*v1 + v2*v2 + v3*v3 + v4*v4 + v5*v5 + v6*v6 + v7*v7;
        #pragma unroll
        for (int o = 4; o; o >>= 1) ss += __shfl_xor_sync(0xffffffffu, ss, o);
        float scale = 1.f / (sqrtf(ss) + EPS);

        float4 r0o, r1o;
        r0o.x = v0 * scale; r0o.y = v1 * scale; r0o.z = v2 * scale; r0o.w = v3 * scale;
        r1o.x = v4 * scale; r1o.y = v5 * scale; r1o.z = v6 * scale; r1o.w = v7 * scale;
        *(float4*)(hout + (size_t)node * 64 + sl * 8)     = r0o;
        *(float4*)(hout + (size_t)node * 64 + sl * 8 + 4) = r1o;
    }
}

// ---------------- stage: MLP head ----------------
__device__ void head_stage(const float* __restrict__ h,
                           const float* __restrict__ mw1,
                           const float* __restrict__ mb1,
                           const float* __restrict__ mw2,
                           const float* __restrict__ mb2,
                           float* __restrict__ out,
                           float* smemf) {
    float* w1s  = smemf;            // 2048
    float* b1s  = smemf + 2048;     // 32
    float* w2s  = smemf + 2080;     // 32
    float* b2sp = smemf + 2112;     // 1

    int tid = threadIdx.x;
    for (int i = tid; i < 64 * 32; i += NTHR) w1s[i] = mw1[i];
    if (tid < 32) { b1s[tid] = mb1[tid]; w2s[tid] = mw2[tid]; }
    if (tid == 0) *b2sp = mb2[0];
    __syncthreads();
    float b2v = *b2sp;

    int lane = tid & 31;
    int warp0 = (blockIdx.x * NTHR + tid) >> 5;
    const int nwarps = (NBLK * NTHR) >> 5;

    for (int node = warp0; node < N_NODES; node += nwarps) {
        float h0 = h[(size_t)node * 64 + lane];
        float h1 = h[(size_t)node * 64 + lane + 32];

        float acc = b1s[lane];
        #pragma unroll
        for (int k = 0; k < 32; ++k) {
            float hk = __shfl_sync(0xffffffffu, h0, k);
            acc = fmaf(hk, w1s[k * 32 + lane], acc);
        }
        #pragma unroll
        for (int k = 0; k < 32; ++k) {
            float hk = __shfl_sync(0xffffffffu, h1, k);
            acc = fmaf(hk, w1s[(k + 32) * 32 + lane], acc);
        }
        acc = fmaxf(acc, 0.f);

        float p = acc * w2s[lane];
        #pragma unroll
        for (int o = 16; o; o >>= 1) p += __shfl_xor_sync(0xffffffffu, p, o);

        if (lane == 0) {
            float z = p + b2v;
            out[node] = 1.f / (1.f + __expf(-z));
        }
    }
}

// ---------------- the persistent mega kernel ----------------
__global__ __launch_bounds__(NTHR)
void mega_kernel(const float* __restrict__ x, const void* __restrict__ ei,
                 const float* __restrict__ w0s, const float* __restrict__ w0n,
                 const float* __restrict__ w1s, const float* __restrict__ w1n,
                 const float* __restrict__ w2s, const float* __restrict__ w2n,
                 const float* __restrict__ mw1, const float* __restrict__ mb1,
                 const float* __restrict__ mw2, const float* __restrict__ mb2,
                 float* __restrict__ out) {
    extern __shared__ float smem[];
    int is64 = g_is64;
    int ph = 0;

    // stage 1: layer-0 GEMM (independent of CSR) + degree count
    gemm_stage<IN_DIM>(x, w0s, w0n, g_s, g_th, smem);
    count_stage(ei, is64);
    grid_barrier(NBLK * ++ph);

    scan_stage(smem);
    grid_barrier(NBLK * ++ph);

    fill_stage(ei, is64);
    grid_barrier(NBLK * ++ph);

    agg_stage(g_th, g_s, g_hA);
    grid_barrier(NBLK * ++ph);

    gemm_stage<HID>(g_hA, w1s, w1n, g_s, g_th, smem);
    grid_barrier(NBLK * ++ph);

    agg_stage(g_th, g_s, g_hB);
    grid_barrier(NBLK * ++ph);

    gemm_stage<HID>(g_hB, w2s, w2n, g_s, g_th, smem);
    grid_barrier(NBLK * ++ph);

    agg_stage(g_th, g_s, g_hA);
    grid_barrier(NBLK * ++ph);

    head_stage(g_hA, mw1, mb1, mw2, mb2, out, smem);
}

// ---------------- launch ----------------
extern "C" void kernel_launch(void* const* d_in, const int* in_sizes, int n_in,
                              void* d_out, int out_size) {
    const float* x   = (const float*)d_in[0];
    const void*  ei  = (const void*)d_in[1];
    const float* w0s = (const float*)d_in[2];
    const float* w0n = (const float*)d_in[3];
    const float* w1s = (const float*)d_in[4];
    const float* w1n = (const float*)d_in[5];
    const float* w2s = (const float*)d_in[6];
    const float* w2n = (const float*)d_in[7];
    const float* mw1 = (const float*)d_in[8];
    const float* mb1 = (const float*)d_in[9];
    const float* mw2 = (const float*)d_in[10];
    const float* mb2 = (const float*)d_in[11];
    float* out = (float*)d_out;

    // dyn smem = max stage need: 2*128*64 (weights) + 32*128 (h tile) floats
    const int SMEM_MEGA = (2 * IN_DIM * 64 + 32 * IN_DIM) * 4;   // 81920
    cudaFuncSetAttribute(mega_kernel,
                         cudaFuncAttributeMaxDynamicSharedMemorySize, SMEM_MEGA);

    const int NB = (N_NODES + 255) / 256;

    init_kernel<<<NB, 256>>>(ei);
    mega_kernel<<<NBLK, NTHR, SMEM_MEGA>>>(x, ei, w0s, w0n, w1s, w1n,
                                           w2s, w2n, mw1, mb1, mw2, mb2, out);
}